// round 9
// baseline (speedup 1.0000x reference)
#include <cuda_runtime.h>
#include <cuda_fp16.h>
#include <math.h>

// VQ on GB300: fp16 HFMA2 screening GEMM (rt=2 measured class) + certified
// window + exact fp32 rescore => bit-exact reference argmins.
#define C_DIM 128
#define HW 4096
#define BN 64
#define N_TILES 4096
#define NTH 256
#define GRID 148
#define NQ 33554432
#define N_TOT 262144
#define CAP 8

// smem byte offsets
#define EH_OFF   0        // half2 eh[c][128]  (65536)
#define ZD_OFF   65536    // half2 zd[c][64] dup (32768)
#define ZF_OFF   98304    // float zf[c][64] (32768)
#define SE_OFF   131072   // se[256]
#define MC_OFF   132096   // Mc[128]
#define AN_OFF   132608   // An[64]
#define WIN_OFF  132864   // win[64]
#define RED_OFF  133120   // RA[4][64], RB[4][64] (2048)
#define CNT_OFF  135168   // cnt[64]
#define CAND_OFF 135424   // cand[64][CAP] (2048)
#define IDX_OFF  137472   // idx_s[64]
#define WS_OFF   137728   // wsum[8]
#define SMEM_BYTES 137792

__device__ double d_loss_arr[GRID];

__device__ __forceinline__ unsigned fkey(float d){
    unsigned u=__float_as_uint(d); return ((int)u<0)?~u:(u|0x80000000u);
}

__global__ void __launch_bounds__(NTH,1)
vq_main(const float* __restrict__ z, const float* __restrict__ emb,
        float* __restrict__ out_q, float* __restrict__ out_idx){
    extern __shared__ char smx[];
    half2* eh =(half2*)(smx+EH_OFF);
    half2* zd =(half2*)(smx+ZD_OFF);
    float* zf =(float*)(smx+ZF_OFF);
    float* se =(float*)(smx+SE_OFF);
    float* Mc =(float*)(smx+MC_OFF);
    float* An =(float*)(smx+AN_OFF);
    float* win=(float*)(smx+WIN_OFF);
    float* RA =(float*)(smx+RED_OFF);
    float* RB =(float*)(smx+RED_OFF+1024);
    int*   cnt =(int*)(smx+CNT_OFF);
    int*   cand=(int*)(smx+CAND_OFF);
    int*   idx_s=(int*)(smx+IDX_OFF);
    float* wsum=(float*)(smx+WS_OFF);

    const int tid=threadIdx.x, lane=tid&31, w=tid>>5;

    // ---- prologue: se (R3-equivalent sequential chain) + eh staging ----
    {
        int k=tid;
        const float4* er=(const float4*)(emb+(size_t)k*C_DIM);
        float s=0.f;
        #pragma unroll 8
        for(int i=0;i<32;++i){
            float4 v=er[i];
            s=__fmaf_rn(v.x,v.x,s); s=__fmaf_rn(v.y,v.y,s);
            s=__fmaf_rn(v.z,v.z,s); s=__fmaf_rn(v.w,v.w,s);
        }
        se[k]=s;
    }
    {
        int j=tid&127, ih=tid>>7;                 // code pair (2j, 2j+1)
        const float* ra=emb+(size_t)(2*j)*C_DIM;
        const float* rb=ra+C_DIM;
        #pragma unroll 4
        for(int i=ih*16;i<ih*16+16;++i){
            float4 a=*(const float4*)(ra+i*4);
            float4 b=*(const float4*)(rb+i*4);
            int c=i*4;
            eh[(c  )*128+j]=__halves2half2(__float2half_rn(a.x),__float2half_rn(b.x));
            eh[(c+1)*128+j]=__halves2half2(__float2half_rn(a.y),__float2half_rn(b.y));
            eh[(c+2)*128+j]=__halves2half2(__float2half_rn(a.z),__float2half_rn(b.z));
            eh[(c+3)*128+j]=__halves2half2(__float2half_rn(a.w),__float2half_rn(b.w));
        }
    }
    __syncthreads();
    if(tid<128){     // Mc[c] = max_k |e_hat|
        float m=0.f;
        const half2* row=eh+tid*128;
        #pragma unroll 8
        for(int j=0;j<128;++j){
            half2 v=row[j];
            m=fmaxf(m,fmaxf(fabsf(__low2float(v)),fabsf(__high2float(v))));
        }
        Mc[tid]=m;
    }
    __syncthreads();

    const int n0=(tid>>5)*8;        // warp owns 8 queries
    const int k0=lane*8;            // lane owns 8 codes (4 half2 pairs)
    float lsum=0.f;

    for(int tile=blockIdx.x; tile<N_TILES; tile+=GRID){
        const int b=tile>>6, hw0=(tile&63)<<6;
        const float* zb=z+(size_t)b*(C_DIM*HW)+hw0;

        // ---- stage z: fp32 + dup'd half2 ----
        #pragma unroll
        for(int i=0;i<8;++i){
            int idx=tid+i*NTH;            // 2048 float4
            int c=idx>>4, n4=(idx&15)<<2;
            float4 v=*(const float4*)(zb+(size_t)c*HW+n4);
            *(float4*)(zf+c*64+n4)=v;
            half2* zp=zd+c*64+n4;
            zp[0]=__half2half2(__float2half_rn(v.x));
            zp[1]=__half2half2(__float2half_rn(v.y));
            zp[2]=__half2half2(__float2half_rn(v.z));
            zp[3]=__half2half2(__float2half_rn(v.w));
        }
        __syncthreads();

        // ---- A_n (exact, order-invariant) and B_n partials ----
        {
            int n=tid&63, part=tid>>6;
            const float* zp=zf+(part*32)*64+n;
            const float* mp=Mc+part*32;
            float a=0.f, bb=0.f;
            #pragma unroll 8
            for(int j=0;j<32;++j){
                float v=zp[j*64];
                a=__fmaf_rn(v,v,a);
                bb=__fmaf_rn(fabsf(v),mp[j],bb);
            }
            RA[part*64+n]=a; RB[part*64+n]=bb;
        }
        __syncthreads();
        if(tid<64){
            int n=tid;
            An[n]=((RA[n]+RA[64+n])+RA[128+n])+RA[192+n];
            float B=RB[n]+RB[64+n]+RB[128+n]+RB[192+n];
            win[n]=B*0.039f+2e-4f;      // certified fp16-chain window (2x safety)
            cnt[n]=0;
        }
        __syncthreads();

        // ---- HFMA2 screening GEMM: 4 sub-chains of 32, fp32 combine ----
        float accG[8][8];
        #pragma unroll
        for(int i=0;i<8;++i)
            #pragma unroll
            for(int j=0;j<8;++j) accG[i][j]=0.f;
        #pragma unroll 1
        for(int sub=0;sub<4;++sub){
            half2 acc[8][4];
            #pragma unroll
            for(int i=0;i<8;++i)
                #pragma unroll
                for(int j=0;j<4;++j) acc[i][j]=__half2half2(__ushort_as_half(0));
            #pragma unroll 4
            for(int cc=0;cc<32;++cc){
                int c=sub*32+cc;
                const uint4* zp=(const uint4*)(zd+c*64+n0);
                uint4 za0=zp[0], za1=zp[1];                  // broadcast
                uint4 eb=*(const uint4*)(eh+c*128+lane*4);   // conflict-free
                half2 zr[8]={*(half2*)&za0.x,*(half2*)&za0.y,*(half2*)&za0.z,*(half2*)&za0.w,
                             *(half2*)&za1.x,*(half2*)&za1.y,*(half2*)&za1.z,*(half2*)&za1.w};
                half2 er[4]={*(half2*)&eb.x,*(half2*)&eb.y,*(half2*)&eb.z,*(half2*)&eb.w};
                #pragma unroll
                for(int i=0;i<8;++i)
                    #pragma unroll
                    for(int j=0;j<4;++j) acc[i][j]=__hfma2(zr[i],er[j],acc[i][j]);
            }
            #pragma unroll
            for(int i=0;i<8;++i)
                #pragma unroll
                for(int j=0;j<4;++j){
                    accG[i][2*j]  +=__low2float(acc[i][j]);
                    accG[i][2*j+1]+=__high2float(acc[i][j]);
                }
        }

        // ---- approx scores, warp-local min, window threshold ----
        float se8[8];
        #pragma unroll
        for(int jj=0;jj<8;++jj) se8[jj]=se[k0+jj];
        float thr8[8];
        #pragma unroll
        for(int i=0;i<8;++i){
            float A=An[n0+i];
            float m=1e30f;
            #pragma unroll
            for(int jj=0;jj<8;++jj){
                float s=__fmaf_rn(-2.f,accG[i][jj],A)+se8[jj];
                accG[i][jj]=s; m=fminf(m,s);
            }
            #pragma unroll
            for(int o=16;o>0;o>>=1) m=fminf(m,__shfl_xor_sync(0xFFFFFFFFu,m,o));
            thr8[i]=m+win[n0+i];
        }
        // ---- candidate collection ----
        #pragma unroll
        for(int i=0;i<8;++i){
            float t=thr8[i];
            #pragma unroll
            for(int jj=0;jj<8;++jj){
                if(accG[i][jj]<=t){
                    int slot=atomicAdd(&cnt[n0+i],1);
                    if(slot<CAP) cand[(n0+i)*CAP+slot]=k0+jj;
                }
            }
        }
        __syncthreads();

        // ---- exact rescore (bit-exact reference semantics, R3 formula) ----
        if(tid<64){
            int q=tid, m=cnt[q], kbest;
            float A=An[q];
            if(m==1){ kbest=cand[q*CAP]; }
            else{
                unsigned long long best=~0ull;
                if(m<=CAP){
                    for(int i=0;i<m;++i){
                        int k=cand[q*CAP+i];
                        const float* ek=emb+(size_t)k*C_DIM;
                        float g=0.f;
                        #pragma unroll 16
                        for(int c=0;c<C_DIM;++c) g=__fmaf_rn(zf[c*64+q],__ldg(ek+c),g);
                        float d=__fadd_rn(__fadd_rn(A,-__fmul_rn(2.0f,g)),se[k]);
                        unsigned long long key=((unsigned long long)fkey(d)<<32)|(unsigned)k;
                        if(key<best) best=key;
                    }
                }else{
                    for(int k=0;k<256;++k){
                        const float* ek=emb+(size_t)k*C_DIM;
                        float g=0.f;
                        #pragma unroll 16
                        for(int c=0;c<C_DIM;++c) g=__fmaf_rn(zf[c*64+q],__ldg(ek+c),g);
                        float d=__fadd_rn(__fadd_rn(A,-__fmul_rn(2.0f,g)),se[k]);
                        unsigned long long key=((unsigned long long)fkey(d)<<32)|(unsigned)k;
                        if(key<best) best=key;
                    }
                }
                kbest=(int)(best&255u);
            }
            idx_s[q]=kbest;
        }
        __syncthreads();

        // ---- epilogue: q_ste = RN(z + RN(q-z)); loss += RN(q-z)^2 ----
        {
            float* outb=out_q+(size_t)b*(C_DIM*HW)+hw0;
            #pragma unroll
            for(int i=0;i<8;++i){
                int idx=tid+i*NTH;
                int c=idx>>4, n4=(idx&15)<<2;
                float4 zv=*(const float4*)(zf+c*64+n4);
                int ka=idx_s[n4],kb=idx_s[n4+1],kc=idx_s[n4+2],kd=idx_s[n4+3];
                float q0=__ldg(emb+(size_t)ka*C_DIM+c);
                float q1=__ldg(emb+(size_t)kb*C_DIM+c);
                float q2=__ldg(emb+(size_t)kc*C_DIM+c);
                float q3=__ldg(emb+(size_t)kd*C_DIM+c);
                float d0=q0-zv.x,d1=q1-zv.y,d2=q2-zv.z,d3=q3-zv.w;
                lsum=__fmaf_rn(d0,d0,lsum); lsum=__fmaf_rn(d1,d1,lsum);
                lsum=__fmaf_rn(d2,d2,lsum); lsum=__fmaf_rn(d3,d3,lsum);
                float4 o=make_float4(zv.x+d0,zv.y+d1,zv.z+d2,zv.w+d3);
                *(float4*)(outb+(size_t)c*HW+n4)=o;
            }
            if(out_idx!=nullptr && tid<64)
                out_idx[(size_t)tile*BN+tid]=(float)idx_s[tid];
        }
        __syncthreads();
    }

    // ---- per-CTA loss slot ----
    #pragma unroll
    for(int o=16;o>0;o>>=1) lsum+=__shfl_xor_sync(0xFFFFFFFFu,lsum,o);
    if(lane==0) wsum[w]=lsum;
    __syncthreads();
    if(tid==0){
        float t=0.f;
        #pragma unroll
        for(int i=0;i<8;++i) t+=wsum[i];
        d_loss_arr[blockIdx.x]=(double)t;
    }
}

__global__ void vq_finalize(float* out_s){
    __shared__ double sh[64];
    int t=threadIdx.x;
    double s=0.0;
    for(int i=t;i<GRID;i+=64) s+=d_loss_arr[i];
    sh[t]=s; __syncthreads();
    if(t==0){
        double tot=0.0;
        for(int i=0;i<64;++i) tot+=sh[i];
        double mse=tot*(1.0/(double)NQ);
        out_s[0]=(float)(0.25*mse);
        out_s[1]=(float)mse;
    }
}

extern "C" void kernel_launch(void* const* d_in, const int* in_sizes, int n_in,
                              void* d_out, int out_size){
    const float *z,*emb;
    if(n_in>=2 && in_sizes[0]==256*C_DIM){ emb=(const float*)d_in[0]; z=(const float*)d_in[1]; }
    else { z=(const float*)d_in[0]; emb=(const float*)d_in[1]; }
    float* out=(float*)d_out;
    cudaFuncSetAttribute(vq_main, cudaFuncAttributeMaxDynamicSharedMemorySize, SMEM_BYTES);
    float* out_idx=nullptr; float* out_s=nullptr;
    long long osz=(long long)out_size;
    if(osz>=(long long)NQ+N_TOT) out_idx=out+NQ;
    if(osz>=(long long)NQ+N_TOT+2) out_s=out+NQ+N_TOT;
    vq_main<<<GRID,NTH,SMEM_BYTES>>>(z,emb,out,out_idx);
    if(out_s) vq_finalize<<<1,64>>>(out_s);
}

// round 10
// speedup vs baseline: 16.3186x; 16.3186x over previous
#include <cuda_runtime.h>
#include <cuda_bf16.h>

// VectorQuantizer on GB300 — bit-exact fp32 emulation, single fused launch.
// Persistent-CTA FFMA2 GEMM + argmin + gather + loss (+in-kernel finalize).
#define C_DIM   128
#define K_CODES 256
#define HW      4096
#define N_TOT   262144
#define BN      64
#define N_TILES (N_TOT / BN)     // 4096
#define NTH     256
#define NQ      33554432
#define GRID    148

// smem layout (floats)
#define E_OFF    0                        // embT [c][k] 32768
#define ZB_OFF   32768                    // 2 x 8192 raw z [buf][c][n]
#define SE_OFF   (ZB_OFF + 16384)         // 256
#define AP_OFF   (SE_OFF + 256)           // 256 partials
#define A_OFF    (AP_OFF + 256)           // 64
#define IDX_OFF  (A_OFF + 64)             // 64 ints
#define WS_OFF   (IDX_OFF + 64)           // 8
#define SMEM_FLOATS (WS_OFF + 8)
#define SMEM_BYTES  (SMEM_FLOATS * 4)     // ~199 KB

__device__ double d_loss_arr[GRID];
__device__ int    d_done = 0;

// two independent IEEE-RN fma chains per instruction (lanes = adjacent k)
#define FMA2(d, a, b) asm("fma.rn.f32x2 %0, %1, %2, %0;" : "+l"(d) : "l"(a), "l"(b))

__device__ __forceinline__ unsigned long long dup2(float x) {
    unsigned long long r;
    unsigned u = __float_as_uint(x);
    asm("mov.b64 %0, {%1, %1};" : "=l"(r) : "r"(u));
    return r;
}

__device__ __forceinline__ void cp16(float* dst_smem, const float* src) {
    unsigned d = (unsigned)__cvta_generic_to_shared(dst_smem);
    asm volatile("cp.async.cg.shared.global [%0], [%1], 16;" :: "r"(d), "l"(src));
}
#define CP_COMMIT() asm volatile("cp.async.commit_group;")
#define CP_WAIT0()  asm volatile("cp.async.wait_group 0;")

// ---------------------------------------------------------------------------
__global__ void __launch_bounds__(NTH, 1)
vq_main(const float* __restrict__ z, const float* __restrict__ emb,
        float* __restrict__ out_q, float* __restrict__ out_idx,
        float* __restrict__ out_s) {
    extern __shared__ float smem[];
    float* e_s   = smem + E_OFF;
    float* zbuf0 = smem + ZB_OFF;
    float* zbuf1 = smem + ZB_OFF + 8192;
    float* se_s  = smem + SE_OFF;
    float* Ap    = smem + AP_OFF;
    float* A_s   = smem + A_OFF;
    int*   idx_s = (int*)(smem + IDX_OFF);
    float* wsum  = smem + WS_OFF;

    const int tid = threadIdx.x;

    // ---- prologue: build embT [c][k] + se in smem directly from gmem ----
    // thread k reads its row (coalesced float4), scatters to e_s[c*256+k]
    // (STS stride 256 floats -> bank = k%32: conflict-free across a warp).
    {
        int k = tid;
        const float4* er = (const float4*)(emb + (size_t)k * C_DIM);
        float s = 0.f;
        #pragma unroll 8
        for (int i = 0; i < 32; ++i) {
            float4 v = er[i];
            int c = i * 4;
            e_s[(c    ) * K_CODES + k] = v.x;
            e_s[(c + 1) * K_CODES + k] = v.y;
            e_s[(c + 2) * K_CODES + k] = v.z;
            e_s[(c + 3) * K_CODES + k] = v.w;
            s = __fmaf_rn(v.x, v.x, s); s = __fmaf_rn(v.y, v.y, s);
            s = __fmaf_rn(v.z, v.z, s); s = __fmaf_rn(v.w, v.w, s);
        }
        se_s[k] = s;   // sequential fused-fma chain, c ascending (R3 numerics)
    }

    const int nG = tid >> 5, kG = tid & 31;
    const int n0 = nG * 8, k0 = kG * 8;
    float lsum_tot = 0.f;

    // ---- prefetch first z tile ----
    int tile = blockIdx.x;
    {
        int b = tile >> 6, hw0 = (tile & 63) << 6;
        const float* zb = z + (size_t)b * (C_DIM * HW) + hw0;
        #pragma unroll
        for (int i = 0; i < 8; ++i) {
            int idx = tid + i * NTH;
            int c = idx >> 4, n4 = (idx & 15) << 2;
            cp16(zbuf0 + c * 64 + n4, zb + (size_t)c * HW + n4);
        }
        CP_COMMIT();
    }

    int buf = 0;
    for (; tile < N_TILES; tile += GRID) {
        float* zcur = buf ? zbuf1 : zbuf0;
        float* znxt = buf ? zbuf0 : zbuf1;

        CP_WAIT0();
        __syncthreads();

        int next = tile + GRID;
        if (next < N_TILES) {
            int b = next >> 6, hw0 = (next & 63) << 6;
            const float* zb = z + (size_t)b * (C_DIM * HW) + hw0;
            #pragma unroll
            for (int i = 0; i < 8; ++i) {
                int idx = tid + i * NTH;
                int c = idx >> 4, n4 = (idx & 15) << 2;
                cp16(znxt + c * 64 + n4, zb + (size_t)c * HW + n4);
            }
            CP_COMMIT();
        }

        // ---- A_n via 4 partial fused-fma chains (argmin-invariant order) ----
        {
            int n = tid & 63, part = tid >> 6;
            const float* zp = zcur + part * 32 * 64 + n;
            float a = 0.f;
            #pragma unroll 8
            for (int c = 0; c < 32; ++c) { float v = zp[c * 64]; a = fmaf(v, v, a); }
            Ap[tid] = a;
        }
        __syncthreads();
        if (tid < 64)
            A_s[tid] = ((Ap[tid] + Ap[64 + tid]) + Ap[128 + tid]) + Ap[192 + tid];
        __syncthreads();

        // ---- mainloop: G[n,k] sequential fused-fma over c = 0..127 ----
        unsigned long long acc[8][4];
        #pragma unroll
        for (int i = 0; i < 8; ++i)
            #pragma unroll
            for (int j = 0; j < 4; ++j) acc[i][j] = 0ULL;

        #pragma unroll 4
        for (int c = 0; c < C_DIM; ++c) {
            const float2* zp = (const float2*)(zcur + c * 64) + (n0 >> 1);
            float2 p0 = zp[0], p1 = zp[1], p2 = zp[2], p3 = zp[3];  // warp-broadcast
            const ulonglong2* ep = (const ulonglong2*)(e_s + c * K_CODES + k0);
            ulonglong2 e0 = ep[0], e1 = ep[1];
            unsigned long long A8[8] = {dup2(p0.x), dup2(p0.y), dup2(p1.x), dup2(p1.y),
                                        dup2(p2.x), dup2(p2.y), dup2(p3.x), dup2(p3.y)};
            unsigned long long B4[4] = {e0.x, e0.y, e1.x, e1.y};
            // j outer / i inner: B4[j] read by 8 consecutive FFMA2s -> .reuse
            #pragma unroll
            for (int j = 0; j < 4; ++j)
                #pragma unroll
                for (int i = 0; i < 8; ++i) FMA2(acc[i][j], A8[i], B4[j]);
        }

        // ---- argmin: d = RN(RN(A - 2G) + se_k), first-index tie-break ----
        #pragma unroll
        for (int i = 0; i < 8; ++i) {
            float An = A_s[n0 + i];
            unsigned long long best = 0ULL;
            #pragma unroll
            for (int j = 0; j < 4; ++j) {
                float2 g = *(float2*)&acc[i][j];
                int ka = k0 + 2 * j, kb = ka + 1;
                float da = __fadd_rn(__fadd_rn(An, -__fmul_rn(2.0f, g.x)), se_s[ka]);
                float db = __fadd_rn(__fadd_rn(An, -__fmul_rn(2.0f, g.y)), se_s[kb]);
                unsigned va = __float_as_uint(da);
                va = ((int)va < 0) ? ~va : (va | 0x80000000u);
                unsigned vb = __float_as_uint(db);
                vb = ((int)vb < 0) ? ~vb : (vb | 0x80000000u);
                unsigned long long keya = ((unsigned long long)(~va) << 32) | (unsigned)(255 - ka);
                unsigned long long keyb = ((unsigned long long)(~vb) << 32) | (unsigned)(255 - kb);
                if (keya > best) best = keya;
                if (keyb > best) best = keyb;
            }
            #pragma unroll
            for (int off = 16; off > 0; off >>= 1) {
                unsigned long long o = __shfl_xor_sync(0xFFFFFFFFu, best, off);
                if (o > best) best = o;
            }
            if (kG == 0) idx_s[n0 + i] = 255 - (int)(best & 0xFFFFFFFFull);
        }
        __syncthreads();

        // ---- epilogue: q_ste = RN(z + RN(q-z)); loss += RN(q-z)^2 ----
        {
            int b = tile >> 6, hw0 = (tile & 63) << 6;
            float* outb = out_q + (size_t)b * (C_DIM * HW) + hw0;
            #pragma unroll
            for (int i = 0; i < 8; ++i) {
                int idx = tid + i * NTH;           // 2048 float4
                int c = idx >> 4, n4 = (idx & 15) << 2;
                float4 zv = *(const float4*)(zcur + c * 64 + n4);
                int ka = idx_s[n4], kb = idx_s[n4 + 1], kc = idx_s[n4 + 2], kd = idx_s[n4 + 3];
                const float* ec = e_s + c * K_CODES;
                float d0 = ec[ka] - zv.x, d1 = ec[kb] - zv.y;
                float d2 = ec[kc] - zv.z, d3 = ec[kd] - zv.w;
                lsum_tot = fmaf(d0, d0, lsum_tot);
                lsum_tot = fmaf(d1, d1, lsum_tot);
                lsum_tot = fmaf(d2, d2, lsum_tot);
                lsum_tot = fmaf(d3, d3, lsum_tot);
                float4 o = make_float4(zv.x + d0, zv.y + d1, zv.z + d2, zv.w + d3);
                *(float4*)(outb + (size_t)c * HW + n4) = o;
            }
            if (out_idx != nullptr && tid < 64)
                out_idx[(size_t)tile * BN + tid] = (float)idx_s[tid];
        }
        buf ^= 1;
    }

    // ---- per-CTA loss slot + last-block in-kernel finalize ----
    #pragma unroll
    for (int off = 16; off > 0; off >>= 1)
        lsum_tot += __shfl_xor_sync(0xFFFFFFFFu, lsum_tot, off);
    if ((tid & 31) == 0) wsum[tid >> 5] = lsum_tot;
    __syncthreads();
    if (tid == 0) {
        float t = 0.f;
        #pragma unroll
        for (int w = 0; w < 8; ++w) t += wsum[w];
        d_loss_arr[blockIdx.x] = (double)t;
        __threadfence();
        int old = atomicAdd(&d_done, 1);
        if (old == GRID - 1) {                 // last block: deterministic sum
            __threadfence();
            double s = 0.0;
            volatile double* la = d_loss_arr;
            for (int i = 0; i < GRID; ++i) s += la[i];
            double mse = s * (1.0 / (double)NQ);
            if (out_s != nullptr) {
                out_s[0] = (float)(0.25 * mse);
                out_s[1] = (float)mse;
            }
            d_done = 0;                        // reset for next graph replay
            __threadfence();
        }
    }
}

extern "C" void kernel_launch(void* const* d_in, const int* in_sizes, int n_in,
                              void* d_out, int out_size) {
    const float *z, *emb;
    if (n_in >= 2 && in_sizes[0] == K_CODES * C_DIM) {
        emb = (const float*)d_in[0];
        z   = (const float*)d_in[1];
    } else {
        z   = (const float*)d_in[0];
        emb = (const float*)d_in[1];
    }
    float* out = (float*)d_out;

    cudaFuncSetAttribute(vq_main, cudaFuncAttributeMaxDynamicSharedMemorySize,
                         SMEM_BYTES);

    float* out_idx = nullptr;
    float* out_s   = nullptr;
    long long osz = (long long)out_size;
    if (osz >= (long long)NQ + N_TOT)     out_idx = out + NQ;
    if (osz >= (long long)NQ + N_TOT + 2) out_s   = out + NQ + N_TOT;

    vq_main<<<GRID, NTH, SMEM_BYTES>>>(z, emb, out, out_idx, out_s);
}

// round 11
// speedup vs baseline: 18.3613x; 1.1252x over previous
#include <cuda_runtime.h>
#include <cuda_bf16.h>

// VectorQuantizer on GB300 — bit-exact fp32 emulation, single fused launch.
// R11: k-split warp tiling to cut e_s LDS traffic 16x (was smem-crossbar bound).
#define C_DIM   128
#define K_CODES 256
#define HW      4096
#define N_TOT   262144
#define BN      64
#define N_TILES (N_TOT / BN)     // 4096
#define NTH     256
#define NQ      33554432
#define GRID    148

// smem layout (floats)
#define E_OFF    0                        // embT [c][k] 32768
#define ZB_OFF   32768                    // 2 x 8192 raw z [buf][c][n]
#define SE_OFF   (ZB_OFF + 16384)         // 256
#define AP_OFF   (SE_OFF + 256)           // 256 partials
#define A_OFF    (AP_OFF + 256)           // 64
#define IDX_OFF  (A_OFF + 64)             // 64 ints
#define WS_OFF   (IDX_OFF + 64)           // 8
#define RED_OFF  (WS_OFF + 8)             // 1024 floats = 512 ull keys [w][n]
#define SMEM_FLOATS (RED_OFF + 1024)
#define SMEM_BYTES  (SMEM_FLOATS * 4)     // ~203 KB

__device__ double d_loss_arr[GRID];
__device__ int    d_done = 0;

// two independent IEEE-RN fma chains per instruction (lanes = adjacent k)
#define FMA2(d, a, b) asm("fma.rn.f32x2 %0, %1, %2, %0;" : "+l"(d) : "l"(a), "l"(b))

__device__ __forceinline__ unsigned long long dup2(float x) {
    unsigned long long r;
    unsigned u = __float_as_uint(x);
    asm("mov.b64 %0, {%1, %1};" : "=l"(r) : "r"(u));
    return r;
}

__device__ __forceinline__ void cp16(float* dst_smem, const float* src) {
    unsigned d = (unsigned)__cvta_generic_to_shared(dst_smem);
    asm volatile("cp.async.cg.shared.global [%0], [%1], 16;" :: "r"(d), "l"(src));
}
#define CP_COMMIT() asm volatile("cp.async.commit_group;")
#define CP_WAIT0()  asm volatile("cp.async.wait_group 0;")

// ---------------------------------------------------------------------------
__global__ void __launch_bounds__(NTH, 1)
vq_main(const float* __restrict__ z, const float* __restrict__ emb,
        float* __restrict__ out_q, float* __restrict__ out_idx,
        float* __restrict__ out_s) {
    extern __shared__ float smem[];
    float* e_s   = smem + E_OFF;
    float* zbuf0 = smem + ZB_OFF;
    float* zbuf1 = smem + ZB_OFF + 8192;
    float* se_s  = smem + SE_OFF;
    float* Ap    = smem + AP_OFF;
    float* A_s   = smem + A_OFF;
    int*   idx_s = (int*)(smem + IDX_OFF);
    float* wsum  = smem + WS_OFF;
    unsigned long long* red = (unsigned long long*)(smem + RED_OFF); // [8][64]

    const int tid  = threadIdx.x;
    const int lane = tid & 31, w = tid >> 5;

    // ---- prologue: build embT [c][k] + se in smem directly from gmem ----
    {
        int k = tid;
        const float4* er = (const float4*)(emb + (size_t)k * C_DIM);
        float s = 0.f;
        #pragma unroll 8
        for (int i = 0; i < 32; ++i) {
            float4 v = er[i];
            int c = i * 4;
            e_s[(c    ) * K_CODES + k] = v.x;
            e_s[(c + 1) * K_CODES + k] = v.y;
            e_s[(c + 2) * K_CODES + k] = v.z;
            e_s[(c + 3) * K_CODES + k] = v.w;
            s = __fmaf_rn(v.x, v.x, s); s = __fmaf_rn(v.y, v.y, s);
            s = __fmaf_rn(v.z, v.z, s); s = __fmaf_rn(v.w, v.w, s);
        }
        se_s[k] = s;   // sequential fused-fma chain, c ascending (R3 numerics)
    }

    // k-split tiling: warp w owns codes [32w, 32w+32); lane quad layout
    const int kq = lane & 3, nq = lane >> 2;
    const int n0 = nq * 8;
    const int k0 = w * 32 + kq * 8;
    float lsum_tot = 0.f;

    // ---- prefetch first z tile ----
    int tile = blockIdx.x;
    {
        int b = tile >> 6, hw0 = (tile & 63) << 6;
        const float* zb = z + (size_t)b * (C_DIM * HW) + hw0;
        #pragma unroll
        for (int i = 0; i < 8; ++i) {
            int idx = tid + i * NTH;
            int c = idx >> 4, n4 = (idx & 15) << 2;
            cp16(zbuf0 + c * 64 + n4, zb + (size_t)c * HW + n4);
        }
        CP_COMMIT();
    }

    int buf = 0;
    for (; tile < N_TILES; tile += GRID) {
        float* zcur = buf ? zbuf1 : zbuf0;
        float* znxt = buf ? zbuf0 : zbuf1;

        CP_WAIT0();
        __syncthreads();

        int next = tile + GRID;
        if (next < N_TILES) {
            int b = next >> 6, hw0 = (next & 63) << 6;
            const float* zb = z + (size_t)b * (C_DIM * HW) + hw0;
            #pragma unroll
            for (int i = 0; i < 8; ++i) {
                int idx = tid + i * NTH;
                int c = idx >> 4, n4 = (idx & 15) << 2;
                cp16(znxt + c * 64 + n4, zb + (size_t)c * HW + n4);
            }
            CP_COMMIT();
        }

        // ---- A_n via 4 partial fused-fma chains (argmin-invariant order) ----
        {
            int n = tid & 63, part = tid >> 6;
            const float* zp = zcur + part * 32 * 64 + n;
            float a = 0.f;
            #pragma unroll 8
            for (int c = 0; c < 32; ++c) { float v = zp[c * 64]; a = fmaf(v, v, a); }
            Ap[tid] = a;
        }
        __syncthreads();
        if (tid < 64)
            A_s[tid] = ((Ap[tid] + Ap[64 + tid]) + Ap[128 + tid]) + Ap[192 + tid];
        __syncthreads();

        // ---- mainloop: G[n,k] sequential fused-fma over c = 0..127 ----
        unsigned long long acc[8][4];
        #pragma unroll
        for (int i = 0; i < 8; ++i)
            #pragma unroll
            for (int j = 0; j < 4; ++j) acc[i][j] = 0ULL;

        #pragma unroll 4
        for (int c = 0; c < C_DIM; ++c) {
            const float4* zp = (const float4*)(zcur + c * 64 + n0);   // 4-way bcast
            float4 q0 = zp[0], q1 = zp[1];
            const ulonglong2* ep = (const ulonglong2*)(e_s + c * K_CODES + k0); // 8-way bcast
            ulonglong2 e0 = ep[0], e1 = ep[1];
            unsigned long long A8[8] = {dup2(q0.x), dup2(q0.y), dup2(q0.z), dup2(q0.w),
                                        dup2(q1.x), dup2(q1.y), dup2(q1.z), dup2(q1.w)};
            unsigned long long B4[4] = {e0.x, e0.y, e1.x, e1.y};
            #pragma unroll
            for (int j = 0; j < 4; ++j)
                #pragma unroll
                for (int i = 0; i < 8; ++i) FMA2(acc[i][j], A8[i], B4[j]);
        }

        // ---- argmin: d = RN(RN(A - 2G) + se_k); quad-reduce then cross-warp ----
        #pragma unroll
        for (int i = 0; i < 8; ++i) {
            float An = A_s[n0 + i];
            unsigned long long best = 0ULL;
            #pragma unroll
            for (int j = 0; j < 4; ++j) {
                float2 g = *(float2*)&acc[i][j];
                int ka = k0 + 2 * j, kb = ka + 1;
                float da = __fadd_rn(__fadd_rn(An, -__fmul_rn(2.0f, g.x)), se_s[ka]);
                float db = __fadd_rn(__fadd_rn(An, -__fmul_rn(2.0f, g.y)), se_s[kb]);
                unsigned va = __float_as_uint(da);
                va = ((int)va < 0) ? ~va : (va | 0x80000000u);
                unsigned vb = __float_as_uint(db);
                vb = ((int)vb < 0) ? ~vb : (vb | 0x80000000u);
                unsigned long long keya = ((unsigned long long)(~va) << 32) | (unsigned)(255 - ka);
                unsigned long long keyb = ((unsigned long long)(~vb) << 32) | (unsigned)(255 - kb);
                if (keya > best) best = keya;
                if (keyb > best) best = keyb;
            }
            // reduce over the 4 lanes of the quad (kq = 0..3)
            #pragma unroll
            for (int off = 1; off < 4; off <<= 1) {
                unsigned long long o = __shfl_xor_sync(0xFFFFFFFFu, best, off);
                if (o > best) best = o;
            }
            if (kq == 0) red[w * 64 + n0 + i] = best;
        }
        __syncthreads();
        if (tid < 64) {   // combine the 8 warps' 32-k slices
            unsigned long long best = red[tid];
            #pragma unroll
            for (int ww = 1; ww < 8; ++ww) {
                unsigned long long o = red[ww * 64 + tid];
                if (o > best) best = o;
            }
            idx_s[tid] = 255 - (int)(best & 0xFFFFFFFFull);
        }
        __syncthreads();

        // ---- epilogue: q_ste = RN(z + RN(q-z)); loss += RN(q-z)^2 ----
        {
            int b = tile >> 6, hw0 = (tile & 63) << 6;
            float* outb = out_q + (size_t)b * (C_DIM * HW) + hw0;
            #pragma unroll
            for (int i = 0; i < 8; ++i) {
                int idx = tid + i * NTH;           // 2048 float4
                int c = idx >> 4, n4 = (idx & 15) << 2;
                float4 zv = *(const float4*)(zcur + c * 64 + n4);
                int ka = idx_s[n4], kb = idx_s[n4 + 1], kc = idx_s[n4 + 2], kd = idx_s[n4 + 3];
                const float* ec = e_s + c * K_CODES;
                float d0 = ec[ka] - zv.x, d1 = ec[kb] - zv.y;
                float d2 = ec[kc] - zv.z, d3 = ec[kd] - zv.w;
                lsum_tot = fmaf(d0, d0, lsum_tot);
                lsum_tot = fmaf(d1, d1, lsum_tot);
                lsum_tot = fmaf(d2, d2, lsum_tot);
                lsum_tot = fmaf(d3, d3, lsum_tot);
                float4 o = make_float4(zv.x + d0, zv.y + d1, zv.z + d2, zv.w + d3);
                *(float4*)(outb + (size_t)c * HW + n4) = o;
            }
            if (out_idx != nullptr && tid < 64)
                out_idx[(size_t)tile * BN + tid] = (float)idx_s[tid];
        }
        buf ^= 1;
    }

    // ---- per-CTA loss slot + last-block in-kernel finalize ----
    #pragma unroll
    for (int off = 16; off > 0; off >>= 1)
        lsum_tot += __shfl_xor_sync(0xFFFFFFFFu, lsum_tot, off);
    if (lane == 0) wsum[w] = lsum_tot;
    __syncthreads();
    if (tid == 0) {
        float t = 0.f;
        #pragma unroll
        for (int ww = 0; ww < 8; ++ww) t += wsum[ww];
        d_loss_arr[blockIdx.x] = (double)t;
        __threadfence();
        int old = atomicAdd(&d_done, 1);
        if (old == GRID - 1) {                 // last block: deterministic sum
            __threadfence();
            double s = 0.0;
            volatile double* la = d_loss_arr;
            for (int i = 0; i < GRID; ++i) s += la[i];
            double mse = s * (1.0 / (double)NQ);
            if (out_s != nullptr) {
                out_s[0] = (float)(0.25 * mse);
                out_s[1] = (float)mse;
            }
            d_done = 0;                        // reset for next graph replay
            __threadfence();
        }
    }
}

extern "C" void kernel_launch(void* const* d_in, const int* in_sizes, int n_in,
                              void* d_out, int out_size) {
    const float *z, *emb;
    if (n_in >= 2 && in_sizes[0] == K_CODES * C_DIM) {
        emb = (const float*)d_in[0];
        z   = (const float*)d_in[1];
    } else {
        z   = (const float*)d_in[0];
        emb = (const float*)d_in[1];
    }
    float* out = (float*)d_out;

    cudaFuncSetAttribute(vq_main, cudaFuncAttributeMaxDynamicSharedMemorySize,
                         SMEM_BYTES);

    float* out_idx = nullptr;
    float* out_s   = nullptr;
    long long osz = (long long)out_size;
    if (osz >= (long long)NQ + N_TOT)     out_idx = out + NQ;
    if (osz >= (long long)NQ + N_TOT + 2) out_s   = out + NQ + N_TOT;

    vq_main<<<GRID, NTH, SMEM_BYTES>>>(z, emb, out, out_idx, out_s);
}